// round 4
// baseline (speedup 1.0000x reference)
#include <cuda_runtime.h>
#include <cuda_bf16.h>
#include <cstdint>
#include <cstddef>

// Problem constants
#define BB   4
#define NTOK 2048
#define DMODEL 1024
#define NH   16
#define HD   64
#define D3   (3 * DMODEL)      // 3072
#define MROWS (BB * NTOK)      // 8192
#define SCALE 0.125f           // 1/sqrt(64)

// Scratch (static device globals — allocation-free)
__device__ float g_qkv[(size_t)MROWS * D3];       // [B*N, 3*D]
__device__ float g_att[(size_t)MROWS * DMODEL];   // [B*N, D]
__device__ float g_wqkvT[(size_t)D3 * DMODEL];    // Wqkv^T [3072,1024]
__device__ float g_woutT[(size_t)DMODEL * DMODEL];// Wout^T [1024,1024]

// ---------------------------------------------------------------------------
// Helpers (sm_80-compatible PTX only — NO tcgen05, harness targets compute_100)
// ---------------------------------------------------------------------------
__device__ __forceinline__ uint32_t f2tf32(float x) {
    uint32_t u; asm("cvt.rna.tf32.f32 %0, %1;" : "=r"(u) : "f"(x));
    return u;
}
__device__ __forceinline__ uint32_t u32(float x) { return __float_as_uint(x); }

#define MMA_TF32(d0, d1, d2, d3, a0, a1, a2, a3, b0, b1)                      \
    asm volatile(                                                              \
        "mma.sync.aligned.m16n8k8.row.col.f32.tf32.tf32.f32 "                  \
        "{%0,%1,%2,%3},{%4,%5,%6,%7},{%8,%9},{%0,%1,%2,%3};"                   \
        : "+f"(d0), "+f"(d1), "+f"(d2), "+f"(d3)                               \
        : "r"(a0), "r"(a1), "r"(a2), "r"(a3), "r"(b0), "r"(b1))

// ---------------------------------------------------------------------------
// Transpose: out[C][R] = in[R][C]
// ---------------------------------------------------------------------------
__global__ __launch_bounds__(256) void transpose_kernel(
    const float* __restrict__ in, float* __restrict__ out, int R, int Cc)
{
    __shared__ float tile[32][33];
    int c0 = blockIdx.x * 32, r0 = blockIdx.y * 32;
    int lx = threadIdx.x & 31, ly = threadIdx.x >> 5;
#pragma unroll
    for (int rr = ly; rr < 32; rr += 8)
        tile[rr][lx] = in[(size_t)(r0 + rr) * Cc + c0 + lx];
    __syncthreads();
#pragma unroll
    for (int rr = ly; rr < 32; rr += 8)
        out[(size_t)(c0 + rr) * R + r0 + lx] = tile[lx][rr];
}

// ---------------------------------------------------------------------------
// 3xTF32 warp-MMA GEMM: C[M,Nn] = A[M,K] @ BT[Nn,K]^T + bias
// BM=128, BN=128, BK=16; 256 threads (8 warps, 4x2); warp tile 32x64.
//
// Smem layout: [kstep(2)][row(128)][16 floats], where the 16 floats encode
// the 8 k-columns in permuted order [0,4,1,5,2,6,3,7], each as (hi, lo).
// A thread's mma fragment (cols tg and tg+4, hi+lo) is then ONE lds.128.
// ---------------------------------------------------------------------------
__device__ __forceinline__ void split_store4(float4 v, float* rowp, int j0) {
#pragma unroll
    for (int q = 0; q < 4; q++) {
        int j = j0 + q;
        int perm = (j < 4) ? (2 * j) : (2 * (j - 4) + 1);
        float x = (&v.x)[q];
        float hf = __uint_as_float(f2tf32(x));
        float lf = x - hf;
        *(float2*)(rowp + perm * 2) = make_float2(hf, lf);
    }
}

__global__ __launch_bounds__(256) void gemm_mma_kernel(
    const float* __restrict__ A, const float* __restrict__ BT,
    const float* __restrict__ bias, float* __restrict__ C,
    int M, int Nn, int K)
{
    __shared__ float As[2][128][16];
    __shared__ float Bs[2][128][16];

    const int t    = threadIdx.x;
    const int wid  = t >> 5, lane = t & 31;
    const int g    = lane >> 2, tg = lane & 3;
    const int wm   = wid >> 1, wn = wid & 1;
    const int m0   = blockIdx.y * 128;
    const int n0   = blockIdx.x * 128;

    float acc[2][8][4];
#pragma unroll
    for (int mt = 0; mt < 2; mt++)
#pragma unroll
        for (int nt = 0; nt < 8; nt++)
#pragma unroll
            for (int i = 0; i < 4; i++) acc[mt][nt][i] = 0.0f;

    const int NT = K / 16;
    float4 ra[2], rb[2];

    // prologue: load tile 0
#pragma unroll
    for (int i = 0; i < 2; i++) {
        int f = t * 2 + i, row = f >> 2, c = f & 3;
        ra[i] = *(const float4*)(A  + (size_t)(m0 + row) * K + c * 4);
        rb[i] = *(const float4*)(BT + (size_t)(n0 + row) * K + c * 4);
    }
#pragma unroll
    for (int i = 0; i < 2; i++) {
        int f = t * 2 + i, row = f >> 2, c = f & 3, s = c >> 1, j0 = (c & 1) * 4;
        split_store4(ra[i], &As[s][row][0], j0);
        split_store4(rb[i], &Bs[s][row][0], j0);
    }
    __syncthreads();

    for (int kt = 0; kt < NT; kt++) {
        if (kt + 1 < NT) {
#pragma unroll
            for (int i = 0; i < 2; i++) {
                int f = t * 2 + i, row = f >> 2, c = f & 3;
                ra[i] = *(const float4*)(A  + (size_t)(m0 + row) * K + (kt + 1) * 16 + c * 4);
                rb[i] = *(const float4*)(BT + (size_t)(n0 + row) * K + (kt + 1) * 16 + c * 4);
            }
        }
#pragma unroll
        for (int s = 0; s < 2; s++) {
            float4 ar0[2], ar1[2];
#pragma unroll
            for (int mt = 0; mt < 2; mt++) {
                ar0[mt] = *(float4*)&As[s][wm * 32 + mt * 16 + g][tg * 4];
                ar1[mt] = *(float4*)&As[s][wm * 32 + mt * 16 + g + 8][tg * 4];
            }
#pragma unroll
            for (int nt = 0; nt < 8; nt++) {
                float4 br = *(float4*)&Bs[s][wn * 64 + nt * 8 + g][tg * 4];
#pragma unroll
                for (int mt = 0; mt < 2; mt++) {
                    float* d = acc[mt][nt];
                    // hi * hi
                    MMA_TF32(d[0], d[1], d[2], d[3],
                             u32(ar0[mt].x), u32(ar1[mt].x),
                             u32(ar0[mt].z), u32(ar1[mt].z),
                             u32(br.x), u32(br.z));
                    // hi * lo
                    MMA_TF32(d[0], d[1], d[2], d[3],
                             u32(ar0[mt].x), u32(ar1[mt].x),
                             u32(ar0[mt].z), u32(ar1[mt].z),
                             u32(br.y), u32(br.w));
                    // lo * hi
                    MMA_TF32(d[0], d[1], d[2], d[3],
                             u32(ar0[mt].y), u32(ar1[mt].y),
                             u32(ar0[mt].w), u32(ar1[mt].w),
                             u32(br.x), u32(br.z));
                }
            }
        }
        __syncthreads();
        if (kt + 1 < NT) {
#pragma unroll
            for (int i = 0; i < 2; i++) {
                int f = t * 2 + i, row = f >> 2, c = f & 3, s = c >> 1, j0 = (c & 1) * 4;
                split_store4(ra[i], &As[s][row][0], j0);
                split_store4(rb[i], &Bs[s][row][0], j0);
            }
            __syncthreads();
        }
    }

    // epilogue: bias + store (m16n8 C layout: c0/c1 at row g, c2/c3 at row g+8)
#pragma unroll
    for (int mt = 0; mt < 2; mt++) {
        int r0 = m0 + wm * 32 + mt * 16 + g;
#pragma unroll
        for (int nt = 0; nt < 8; nt++) {
            int cc = n0 + wn * 64 + nt * 8 + tg * 2;
            float2 bv = *(const float2*)(bias + cc);
            float* d = acc[mt][nt];
            *(float2*)(C + (size_t)r0 * Nn + cc) =
                make_float2(d[0] + bv.x, d[1] + bv.y);
            *(float2*)(C + (size_t)(r0 + 8) * Nn + cc) =
                make_float2(d[2] + bv.x, d[3] + bv.y);
        }
    }
}

// ---------------------------------------------------------------------------
// Flash attention (unchanged fp32 SIMT kernel from round 0)
// ---------------------------------------------------------------------------
#define APAD 68

__global__ __launch_bounds__(256) void attn_kernel(
    const float* __restrict__ qkv, float* __restrict__ out)
{
    extern __shared__ float smf[];
    float* Qs = smf;
    float* Ks = Qs + 64 * APAD;
    float* Vs = Ks + 64 * APAD;
    float* Ps = Vs + 64 * APAD;

    const int t  = threadIdx.x;
    const int q0 = blockIdx.x << 6;
    const int h  = blockIdx.y;
    const int b  = blockIdx.z;

    const size_t base = (size_t)b * NTOK * D3 + (size_t)h * HD;
    const float* Qg = qkv + base;
    const float* Kg = qkv + base + DMODEL;
    const float* Vg = qkv + base + 2 * DMODEL;

    const int lr = t >> 4;
    const int lc = (t & 15) << 2;

#pragma unroll
    for (int p = 0; p < 4; p++) {
        int r = lr + (p << 4);
        *(float4*)(Qs + r * APAD + lc) =
            *(const float4*)(Qg + (size_t)(q0 + r) * D3 + lc);
    }

    const int tx = t & 15;
    const int ty = t >> 4;

    float m[4], l[4], o[4][4];
#pragma unroll
    for (int i = 0; i < 4; i++) {
        m[i] = -1e30f; l[i] = 0.0f;
#pragma unroll
        for (int j = 0; j < 4; j++) o[i][j] = 0.0f;
    }

    for (int kt = 0; kt < NTOK / 64; kt++) {
        __syncthreads();
        const int k0 = kt << 6;
#pragma unroll
        for (int p = 0; p < 4; p++) {
            int r = lr + (p << 4);
            *(float4*)(Ks + r * APAD + lc) =
                *(const float4*)(Kg + (size_t)(k0 + r) * D3 + lc);
            *(float4*)(Vs + r * APAD + lc) =
                *(const float4*)(Vg + (size_t)(k0 + r) * D3 + lc);
        }
        __syncthreads();

        float s[4][4];
#pragma unroll
        for (int i = 0; i < 4; i++)
#pragma unroll
            for (int j = 0; j < 4; j++) s[i][j] = 0.0f;

#pragma unroll 4
        for (int d = 0; d < HD; d += 4) {
            float4 qv[4], kv[4];
#pragma unroll
            for (int i = 0; i < 4; i++)
                qv[i] = *(const float4*)(Qs + (ty * 4 + i) * APAD + d);
#pragma unroll
            for (int j = 0; j < 4; j++)
                kv[j] = *(const float4*)(Ks + (tx * 4 + j) * APAD + d);
#pragma unroll
            for (int i = 0; i < 4; i++)
#pragma unroll
                for (int j = 0; j < 4; j++)
                    s[i][j] += qv[i].x * kv[j].x + qv[i].y * kv[j].y +
                               qv[i].z * kv[j].z + qv[i].w * kv[j].w;
        }

#pragma unroll
        for (int i = 0; i < 4; i++) {
#pragma unroll
            for (int j = 0; j < 4; j++) s[i][j] *= SCALE;
            float mx = fmaxf(fmaxf(s[i][0], s[i][1]), fmaxf(s[i][2], s[i][3]));
#pragma unroll
            for (int off = 1; off < 16; off <<= 1)
                mx = fmaxf(mx, __shfl_xor_sync(0xffffffffu, mx, off));
            float mnew = fmaxf(m[i], mx);
            float corr = __expf(m[i] - mnew);
            float psum = 0.0f;
#pragma unroll
            for (int j = 0; j < 4; j++) {
                float p = __expf(s[i][j] - mnew);
                s[i][j] = p;
                psum += p;
            }
#pragma unroll
            for (int off = 1; off < 16; off <<= 1)
                psum += __shfl_xor_sync(0xffffffffu, psum, off);
            l[i] = l[i] * corr + psum;
            m[i] = mnew;
#pragma unroll
            for (int j = 0; j < 4; j++) o[i][j] *= corr;
            float4 pw = make_float4(s[i][0], s[i][1], s[i][2], s[i][3]);
            *(float4*)(Ps + (ty * 4 + i) * APAD + tx * 4) = pw;
        }
        __syncthreads();

#pragma unroll 4
        for (int k = 0; k < 64; k += 4) {
            float pr[4][4];
#pragma unroll
            for (int i = 0; i < 4; i++) {
                float4 pv = *(const float4*)(Ps + (ty * 4 + i) * APAD + k);
                pr[i][0] = pv.x; pr[i][1] = pv.y; pr[i][2] = pv.z; pr[i][3] = pv.w;
            }
#pragma unroll
            for (int kk = 0; kk < 4; kk++) {
                float4 vv = *(const float4*)(Vs + (k + kk) * APAD + (tx << 2));
#pragma unroll
                for (int i = 0; i < 4; i++) {
                    float p = pr[i][kk];
                    o[i][0] += p * vv.x;
                    o[i][1] += p * vv.y;
                    o[i][2] += p * vv.z;
                    o[i][3] += p * vv.w;
                }
            }
        }
    }

#pragma unroll
    for (int i = 0; i < 4; i++) {
        float inv = 1.0f / l[i];
        float4 r;
        r.x = o[i][0] * inv;
        r.y = o[i][1] * inv;
        r.z = o[i][2] * inv;
        r.w = o[i][3] * inv;
        int q = q0 + ty * 4 + i;
        *(float4*)(out + ((size_t)(b * NTOK + q)) * DMODEL + h * HD + (tx << 2)) = r;
    }
}

// ---------------------------------------------------------------------------
// Launcher
// ---------------------------------------------------------------------------
extern "C" void kernel_launch(void* const* d_in, const int* in_sizes, int n_in,
                              void* d_out, int out_size)
{
    const float* x    = (const float*)d_in[0];
    const float* Wqkv = (const float*)d_in[1];
    const float* bqkv = (const float*)d_in[2];
    const float* Wout = (const float*)d_in[3];
    const float* bout = (const float*)d_in[4];
    float* out = (float*)d_out;

    float *qkv = nullptr, *att = nullptr, *wqkvT = nullptr, *woutT = nullptr;
    cudaGetSymbolAddress((void**)&qkv,   g_qkv);
    cudaGetSymbolAddress((void**)&att,   g_att);
    cudaGetSymbolAddress((void**)&wqkvT, g_wqkvT);
    cudaGetSymbolAddress((void**)&woutT, g_woutT);

    // Idempotent, called every launch (no static guards per harness rules)
    cudaFuncSetAttribute(attn_kernel,
                         cudaFuncAttributeMaxDynamicSharedMemorySize,
                         4 * 64 * APAD * (int)sizeof(float));

    // 0) Transpose weights to K-major for the B operand
    transpose_kernel<<<dim3(D3 / 32, DMODEL / 32), 256>>>(Wqkv, wqkvT, DMODEL, D3);
    transpose_kernel<<<dim3(DMODEL / 32, DMODEL / 32), 256>>>(Wout, woutT, DMODEL, DMODEL);

    // 1) QKV projection (3xTF32 warp-MMA)
    {
        dim3 grid(D3 / 128, MROWS / 128);
        gemm_mma_kernel<<<grid, 256>>>(x, wqkvT, bqkv, qkv, MROWS, D3, DMODEL);
    }
    // 2) Attention (fp32 SIMT, unchanged)
    {
        const int attn_smem = 4 * 64 * APAD * (int)sizeof(float);
        dim3 grid(NTOK / 64, NH, BB);
        attn_kernel<<<grid, 256, attn_smem>>>(qkv, att);
    }
    // 3) Output projection (3xTF32 warp-MMA)
    {
        dim3 grid(DMODEL / 128, MROWS / 128);
        gemm_mma_kernel<<<grid, 256>>>(att, woutT, bout, out, MROWS, DMODEL, DMODEL);
    }
}

// round 5
// speedup vs baseline: 2.8021x; 2.8021x over previous
#include <cuda_runtime.h>
#include <cuda_fp16.h>
#include <cuda_bf16.h>
#include <cstdint>
#include <cstddef>

// Problem constants
#define BB   4
#define NTOK 2048
#define DMODEL 1024
#define NH   16
#define HD   64
#define D3   (3 * DMODEL)      // 3072
#define MROWS (BB * NTOK)      // 8192
#define SCALE 0.125f           // 1/sqrt(64)

// Scratch (static device globals — allocation-free)
__device__ float g_qkv[(size_t)MROWS * D3];       // [B*N, 3*D]
__device__ float g_att[(size_t)MROWS * DMODEL];   // [B*N, D]
__device__ float g_wqkvT[(size_t)D3 * DMODEL];    // Wqkv^T [3072,1024]
__device__ float g_woutT[(size_t)DMODEL * DMODEL];// Wout^T [1024,1024]

// ---------------------------------------------------------------------------
// fp16 split helpers + mma.sync m16n8k16 (sm_80-compatible PTX)
// ---------------------------------------------------------------------------
__device__ __forceinline__ void split2(float a, float b, uint32_t& hi, uint32_t& lo) {
    __half2 h = __floats2half2_rn(a, b);
    float2 hf = __half22float2(h);
    __half2 l = __floats2half2_rn(a - hf.x, b - hf.y);
    hi = *reinterpret_cast<uint32_t*>(&h);
    lo = *reinterpret_cast<uint32_t*>(&l);
}

// Store one k-pair (k=2p,2p+1) as (hi,lo) words into a 16-word row.
// Group layout: group q (words 4q..4q+3) = [hi_q, lo_q, hi_{q+4}, lo_{q+4}].
__device__ __forceinline__ void store_pair(uint32_t* row, int p, float e0, float e1) {
    uint32_t hi, lo;
    split2(e0, e1, hi, lo);
    int w = (p & 3) * 4 + ((p >> 2) << 1);
    *(uint2*)(row + w) = make_uint2(hi, lo);
}

#define MMA_F16(d, a0, a1, a2, a3, b0, b1)                                     \
    asm volatile(                                                              \
        "mma.sync.aligned.m16n8k16.row.col.f32.f16.f16.f32 "                   \
        "{%0,%1,%2,%3},{%4,%5,%6,%7},{%8,%9},{%0,%1,%2,%3};"                   \
        : "+f"((d)[0]), "+f"((d)[1]), "+f"((d)[2]), "+f"((d)[3])               \
        : "r"(a0), "r"(a1), "r"(a2), "r"(a3), "r"(b0), "r"(b1))

// ---------------------------------------------------------------------------
// Transpose: out[C][R] = in[R][C]
// ---------------------------------------------------------------------------
__global__ __launch_bounds__(256) void transpose_kernel(
    const float* __restrict__ in, float* __restrict__ out, int R, int Cc)
{
    __shared__ float tile[32][33];
    int c0 = blockIdx.x * 32, r0 = blockIdx.y * 32;
    int lx = threadIdx.x & 31, ly = threadIdx.x >> 5;
#pragma unroll
    for (int rr = ly; rr < 32; rr += 8)
        tile[rr][lx] = in[(size_t)(r0 + rr) * Cc + c0 + lx];
    __syncthreads();
#pragma unroll
    for (int rr = ly; rr < 32; rr += 8)
        out[(size_t)(c0 + rr) * R + r0 + lx] = tile[lx][rr];
}

// ---------------------------------------------------------------------------
// fp16x3 warp-MMA GEMM: C[M,Nn] = A[M,K] @ BT[Nn,K]^T + bias
// BM=128, BN=128, BK=16; 256 threads (8 warps, 4x2); warp tile 32x64.
// Each smem row = 16 uint32 (hi/lo interleaved pairs); one operand fragment
// (hi+lo) = one conflict-free lds.128.
// ---------------------------------------------------------------------------
__global__ __launch_bounds__(256) void gemm_f16_kernel(
    const float* __restrict__ A, const float* __restrict__ BT,
    const float* __restrict__ bias, float* __restrict__ C,
    int M, int Nn, int K)
{
    __shared__ uint32_t As[2][128 * 16];
    __shared__ uint32_t Bs[2][128 * 16];

    const int t    = threadIdx.x;
    const int wid  = t >> 5, lane = t & 31;
    const int g    = lane >> 2, tg = lane & 3;
    const int wm   = wid >> 1, wn = wid & 1;
    const int m0   = blockIdx.y * 128;
    const int n0   = blockIdx.x * 128;

    float acc[2][8][4];
#pragma unroll
    for (int mt = 0; mt < 2; mt++)
#pragma unroll
        for (int nt = 0; nt < 8; nt++)
#pragma unroll
            for (int i = 0; i < 4; i++) acc[mt][nt][i] = 0.0f;

    const int NT = K / 16;
    float4 ra[2], rb[2];

    // prologue: load + store tile 0 into buffer 0
#pragma unroll
    for (int i = 0; i < 2; i++) {
        int f = t * 2 + i, row = f >> 2, c = f & 3;
        ra[i] = *(const float4*)(A  + (size_t)(m0 + row) * K + c * 4);
        rb[i] = *(const float4*)(BT + (size_t)(n0 + row) * K + c * 4);
    }
#pragma unroll
    for (int i = 0; i < 2; i++) {
        int f = t * 2 + i, row = f >> 2, c = f & 3;
        store_pair(&As[0][row * 16], 2 * c,     ra[i].x, ra[i].y);
        store_pair(&As[0][row * 16], 2 * c + 1, ra[i].z, ra[i].w);
        store_pair(&Bs[0][row * 16], 2 * c,     rb[i].x, rb[i].y);
        store_pair(&Bs[0][row * 16], 2 * c + 1, rb[i].z, rb[i].w);
    }
    __syncthreads();

    for (int kt = 0; kt < NT; kt++) {
        const int b = kt & 1;
        if (kt + 1 < NT) {
#pragma unroll
            for (int i = 0; i < 2; i++) {
                int f = t * 2 + i, row = f >> 2, c = f & 3;
                ra[i] = *(const float4*)(A  + (size_t)(m0 + row) * K + (kt + 1) * 16 + c * 4);
                rb[i] = *(const float4*)(BT + (size_t)(n0 + row) * K + (kt + 1) * 16 + c * 4);
            }
        }
        // compute on buffer b
        uint4 af[2][2];
#pragma unroll
        for (int mt = 0; mt < 2; mt++) {
            af[mt][0] = *(uint4*)&As[b][(wm * 32 + mt * 16 + g) * 16 + tg * 4];
            af[mt][1] = *(uint4*)&As[b][(wm * 32 + mt * 16 + g + 8) * 16 + tg * 4];
        }
#pragma unroll
        for (int nt = 0; nt < 8; nt++) {
            uint4 bf = *(uint4*)&Bs[b][(wn * 64 + nt * 8 + g) * 16 + tg * 4];
#pragma unroll
            for (int mt = 0; mt < 2; mt++) {
                float* d = acc[mt][nt];
                // hi*hi
                MMA_F16(d, af[mt][0].x, af[mt][1].x, af[mt][0].z, af[mt][1].z,
                        bf.x, bf.z);
                // hi*lo
                MMA_F16(d, af[mt][0].x, af[mt][1].x, af[mt][0].z, af[mt][1].z,
                        bf.y, bf.w);
                // lo*hi
                MMA_F16(d, af[mt][0].y, af[mt][1].y, af[mt][0].w, af[mt][1].w,
                        bf.x, bf.z);
            }
        }
        if (kt + 1 < NT) {
            const int nb = b ^ 1;
#pragma unroll
            for (int i = 0; i < 2; i++) {
                int f = t * 2 + i, row = f >> 2, c = f & 3;
                store_pair(&As[nb][row * 16], 2 * c,     ra[i].x, ra[i].y);
                store_pair(&As[nb][row * 16], 2 * c + 1, ra[i].z, ra[i].w);
                store_pair(&Bs[nb][row * 16], 2 * c,     rb[i].x, rb[i].y);
                store_pair(&Bs[nb][row * 16], 2 * c + 1, rb[i].z, rb[i].w);
            }
        }
        __syncthreads();
    }

    // epilogue: bias + store
#pragma unroll
    for (int mt = 0; mt < 2; mt++) {
        int r0 = m0 + wm * 32 + mt * 16 + g;
#pragma unroll
        for (int nt = 0; nt < 8; nt++) {
            int cc = n0 + wn * 64 + nt * 8 + tg * 2;
            float2 bv = *(const float2*)(bias + cc);
            float* d = acc[mt][nt];
            *(float2*)(C + (size_t)r0 * Nn + cc) =
                make_float2(d[0] + bv.x, d[1] + bv.y);
            *(float2*)(C + (size_t)(r0 + 8) * Nn + cc) =
                make_float2(d[2] + bv.x, d[3] + bv.y);
        }
    }
}

// ---------------------------------------------------------------------------
// Flash attention with fp16x3 warp-MMA.
// CTA: 128 q-rows for one (b,h); 8 warps, each owns 16 q-rows (one m16).
// Streams 64-key tiles; per-row softmax stats live in quads (shfl only).
// Smem rows have 4 k16-chunks (256B); chunk index XOR row&3 kills conflicts.
// ---------------------------------------------------------------------------
#define ATT_SMEM_BYTES ((128 + 64 + 64) * 4 * 16 * 4)  // 65536

__device__ __forceinline__ uint32_t* att_row(uint32_t* base, int row, int chunk) {
    return base + (row * 4 + (chunk ^ (row & 3))) * 16;
}

__global__ __launch_bounds__(256) void attn_mma_kernel(
    const float* __restrict__ qkv, float* __restrict__ out)
{
    extern __shared__ uint32_t sm[];
    uint32_t* Qs = sm;              // 128 rows * 4 chunks * 16 words = 8192
    uint32_t* Ks = sm + 8192;       // 64 * 4 * 16 = 4096
    uint32_t* Vt = sm + 12288;      // 64 * 4 * 16 = 4096 (rows = hd, k = key)

    const int t    = threadIdx.x;
    const int wid  = t >> 5, lane = t & 31;
    const int g    = lane >> 2, tg = lane & 3;
    const int q0   = blockIdx.x * 128;
    const int h    = blockIdx.y;
    const int b    = blockIdx.z;

    const size_t base = (size_t)b * NTOK * D3 + (size_t)h * HD;
    const float* Qg = qkv + base;
    const float* Kg = qkv + base + DMODEL;
    const float* Vg = qkv + base + 2 * DMODEL;

    // ---- Load Q tile 128x64 -> smem fp16 hi/lo (8 float4 per thread) ----
#pragma unroll
    for (int i = 0; i < 8; i++) {
        int f = i * 256 + t, row = f >> 4, c = f & 15;
        float4 v = *(const float4*)(Qg + (size_t)(q0 + row) * D3 + c * 4);
        uint32_t* rp = att_row(Qs, row, c >> 2);
        int p0 = (c & 3) * 2;
        store_pair(rp, p0,     v.x, v.y);
        store_pair(rp, p0 + 1, v.z, v.w);
    }

    float m0f = -1e30f, m1f = -1e30f, l0 = 0.0f, l1 = 0.0f;
    float oacc[8][4];
#pragma unroll
    for (int nt = 0; nt < 8; nt++)
#pragma unroll
        for (int i = 0; i < 4; i++) oacc[nt][i] = 0.0f;

    const int vkp  = t >> 3;          // key-pair 0..31
    const int vhd0 = (t & 7) * 8;     // hd base

    for (int kt = 0; kt < NTOK / 64; kt++) {
        const int k0 = kt * 64;
        __syncthreads();  // prior tile's consumers done before overwrite

        // ---- K tile 64x64 (4 float4/thread) ----
#pragma unroll
        for (int i = 0; i < 4; i++) {
            int f = i * 256 + t, row = f >> 4, c = f & 15;
            float4 v = *(const float4*)(Kg + (size_t)(k0 + row) * D3 + c * 4);
            uint32_t* rp = att_row(Ks, row, c >> 2);
            int p0 = (c & 3) * 2;
            store_pair(rp, p0,     v.x, v.y);
            store_pair(rp, p0 + 1, v.z, v.w);
        }
        // ---- V tile transposed: Vt[hd][key] (4 float4/thread) ----
        {
            const float* v0p = Vg + (size_t)(k0 + 2 * vkp) * D3 + vhd0;
            const float* v1p = v0p + D3;
            float4 v0a = *(const float4*)(v0p);
            float4 v0b = *(const float4*)(v0p + 4);
            float4 v1a = *(const float4*)(v1p);
            float4 v1b = *(const float4*)(v1p + 4);
            const float* e0 = &v0a.x;  // v0a,v0b contiguous in regs? use arrays
            float va[8] = {v0a.x, v0a.y, v0a.z, v0a.w, v0b.x, v0b.y, v0b.z, v0b.w};
            float vb[8] = {v1a.x, v1a.y, v1a.z, v1a.w, v1b.x, v1b.y, v1b.z, v1b.w};
            (void)e0;
#pragma unroll
            for (int j = 0; j < 8; j++) {
                uint32_t* rp = att_row(Vt, vhd0 + j, vkp >> 3);
                store_pair(rp, vkp & 7, va[j], vb[j]);
            }
        }
        __syncthreads();

        // ---- S = Q K^T (3-term fp16), warp rows wid*16..+15 ----
        float sacc[8][4];
#pragma unroll
        for (int nt = 0; nt < 8; nt++)
#pragma unroll
            for (int i = 0; i < 4; i++) sacc[nt][i] = 0.0f;

#pragma unroll
        for (int ks = 0; ks < 4; ks++) {
            uint4 qa = *(uint4*)(att_row(Qs, wid * 16 + g,     ks) + tg * 4);
            uint4 qb = *(uint4*)(att_row(Qs, wid * 16 + g + 8, ks) + tg * 4);
#pragma unroll
            for (int nt = 0; nt < 8; nt++) {
                uint4 kf = *(uint4*)(att_row(Ks, nt * 8 + g, ks) + tg * 4);
                float* d = sacc[nt];
                MMA_F16(d, qa.x, qb.x, qa.z, qb.z, kf.x, kf.z);  // hi*hi
                MMA_F16(d, qa.x, qb.x, qa.z, qb.z, kf.y, kf.w);  // hi*lo
                MMA_F16(d, qa.y, qb.y, qa.w, qb.w, kf.x, kf.z);  // lo*hi
            }
        }

        // ---- online softmax (rows r0 = wid*16+g, r1 = +8) ----
        float mx0 = -1e30f, mx1 = -1e30f;
#pragma unroll
        for (int nt = 0; nt < 8; nt++) {
            sacc[nt][0] *= SCALE; sacc[nt][1] *= SCALE;
            sacc[nt][2] *= SCALE; sacc[nt][3] *= SCALE;
            mx0 = fmaxf(mx0, fmaxf(sacc[nt][0], sacc[nt][1]));
            mx1 = fmaxf(mx1, fmaxf(sacc[nt][2], sacc[nt][3]));
        }
        mx0 = fmaxf(mx0, __shfl_xor_sync(0xffffffffu, mx0, 1));
        mx0 = fmaxf(mx0, __shfl_xor_sync(0xffffffffu, mx0, 2));
        mx1 = fmaxf(mx1, __shfl_xor_sync(0xffffffffu, mx1, 1));
        mx1 = fmaxf(mx1, __shfl_xor_sync(0xffffffffu, mx1, 2));

        float mn0 = fmaxf(m0f, mx0), mn1 = fmaxf(m1f, mx1);
        float c0 = __expf(m0f - mn0), c1 = __expf(m1f - mn1);
        m0f = mn0; m1f = mn1;

        float s0 = 0.0f, s1 = 0.0f;
#pragma unroll
        for (int nt = 0; nt < 8; nt++) {
            sacc[nt][0] = __expf(sacc[nt][0] - mn0);
            sacc[nt][1] = __expf(sacc[nt][1] - mn0);
            sacc[nt][2] = __expf(sacc[nt][2] - mn1);
            sacc[nt][3] = __expf(sacc[nt][3] - mn1);
            s0 += sacc[nt][0] + sacc[nt][1];
            s1 += sacc[nt][2] + sacc[nt][3];
        }
        s0 += __shfl_xor_sync(0xffffffffu, s0, 1);
        s0 += __shfl_xor_sync(0xffffffffu, s0, 2);
        s1 += __shfl_xor_sync(0xffffffffu, s1, 1);
        s1 += __shfl_xor_sync(0xffffffffu, s1, 2);
        l0 = l0 * c0 + s0;
        l1 = l1 * c1 + s1;
#pragma unroll
        for (int nt = 0; nt < 8; nt++) {
            oacc[nt][0] *= c0; oacc[nt][1] *= c0;
            oacc[nt][2] *= c1; oacc[nt][3] *= c1;
        }

        // ---- O += P V (3-term fp16); S C-frag == PV A-frag layout ----
#pragma unroll
        for (int s = 0; s < 4; s++) {
            uint32_t ah0, al0, ah1, al1, ah2, al2, ah3, al3;
            split2(sacc[2 * s][0],     sacc[2 * s][1],     ah0, al0);  // row g,   k lo8
            split2(sacc[2 * s][2],     sacc[2 * s][3],     ah1, al1);  // row g+8
            split2(sacc[2 * s + 1][0], sacc[2 * s + 1][1], ah2, al2);  // row g,   k hi8
            split2(sacc[2 * s + 1][2], sacc[2 * s + 1][3], ah3, al3);  // row g+8
#pragma unroll
            for (int nt = 0; nt < 8; nt++) {
                uint4 vf = *(uint4*)(att_row(Vt, nt * 8 + g, s) + tg * 4);
                float* d = oacc[nt];
                MMA_F16(d, ah0, ah1, ah2, ah3, vf.x, vf.z);  // p_hi * v_hi
                MMA_F16(d, ah0, ah1, ah2, ah3, vf.y, vf.w);  // p_hi * v_lo
                MMA_F16(d, al0, al1, al2, al3, vf.x, vf.z);  // p_lo * v_hi
            }
        }
    }

    // ---- normalize + write out[b, q, h*64 + col] ----
    float inv0 = 1.0f / l0, inv1 = 1.0f / l1;
    int r0 = q0 + wid * 16 + g;
#pragma unroll
    for (int nt = 0; nt < 8; nt++) {
        int cc = h * HD + nt * 8 + tg * 2;
        *(float2*)(out + (size_t)(b * NTOK + r0) * DMODEL + cc) =
            make_float2(oacc[nt][0] * inv0, oacc[nt][1] * inv0);
        *(float2*)(out + (size_t)(b * NTOK + r0 + 8) * DMODEL + cc) =
            make_float2(oacc[nt][2] * inv1, oacc[nt][3] * inv1);
    }
}

// ---------------------------------------------------------------------------
// Launcher
// ---------------------------------------------------------------------------
extern "C" void kernel_launch(void* const* d_in, const int* in_sizes, int n_in,
                              void* d_out, int out_size)
{
    const float* x    = (const float*)d_in[0];
    const float* Wqkv = (const float*)d_in[1];
    const float* bqkv = (const float*)d_in[2];
    const float* Wout = (const float*)d_in[3];
    const float* bout = (const float*)d_in[4];
    float* out = (float*)d_out;

    float *qkv = nullptr, *att = nullptr, *wqkvT = nullptr, *woutT = nullptr;
    cudaGetSymbolAddress((void**)&qkv,   g_qkv);
    cudaGetSymbolAddress((void**)&att,   g_att);
    cudaGetSymbolAddress((void**)&wqkvT, g_wqkvT);
    cudaGetSymbolAddress((void**)&woutT, g_woutT);

    cudaFuncSetAttribute(attn_mma_kernel,
                         cudaFuncAttributeMaxDynamicSharedMemorySize,
                         ATT_SMEM_BYTES);

    // 0) Transpose weights to K-major for the B operand
    transpose_kernel<<<dim3(D3 / 32, DMODEL / 32), 256>>>(Wqkv, wqkvT, DMODEL, D3);
    transpose_kernel<<<dim3(DMODEL / 32, DMODEL / 32), 256>>>(Wout, woutT, DMODEL, DMODEL);

    // 1) QKV projection (fp16x3 warp-MMA)
    {
        dim3 grid(D3 / 128, MROWS / 128);
        gemm_f16_kernel<<<grid, 256>>>(x, wqkvT, bqkv, qkv, MROWS, D3, DMODEL);
    }
    // 2) Attention (fp16x3 warp-MMA flash)
    {
        dim3 grid(NTOK / 128, NH, BB);
        attn_mma_kernel<<<grid, 256, ATT_SMEM_BYTES>>>(qkv, att);
    }
    // 3) Output projection (fp16x3 warp-MMA)
    {
        dim3 grid(DMODEL / 128, MROWS / 128);
        gemm_f16_kernel<<<grid, 256>>>(att, woutT, bout, out, MROWS, DMODEL, DMODEL);
    }
}

// round 6
// speedup vs baseline: 4.0242x; 1.4362x over previous
#include <cuda_runtime.h>
#include <cuda_fp16.h>
#include <cstdint>
#include <cstddef>

// Problem constants
#define BB     4
#define NTOK   2048
#define DMODEL 1024
#define NH     16
#define HD     64
#define D3     (3 * DMODEL)    // 3072
#define MROWS  (BB * NTOK)     // 8192
#define SCALE  0.125f          // 1/sqrt(64)

// Scratch (static device globals — allocation-free). All operands pre-split
// into fp16 (hi, lo) pairs so hot loops do zero conversion work.
__device__ __half g_x_h[(size_t)MROWS * DMODEL];
__device__ __half g_x_l[(size_t)MROWS * DMODEL];
__device__ __half g_wqkvT_h[(size_t)D3 * DMODEL];
__device__ __half g_wqkvT_l[(size_t)D3 * DMODEL];
__device__ __half g_woutT_h[(size_t)DMODEL * DMODEL];
__device__ __half g_woutT_l[(size_t)DMODEL * DMODEL];
__device__ __half g_qkv_h[(size_t)MROWS * D3];
__device__ __half g_qkv_l[(size_t)MROWS * D3];
__device__ __half g_att_h[(size_t)MROWS * DMODEL];
__device__ __half g_att_l[(size_t)MROWS * DMODEL];

// ---------------------------------------------------------------------------
// Helpers (sm_80-era PTX only: mma.sync / ldmatrix / cp.async)
// ---------------------------------------------------------------------------
__device__ __forceinline__ void split2(float a, float b, uint32_t& hi, uint32_t& lo) {
    __half2 h = __floats2half2_rn(a, b);
    float2 hf = __half22float2(h);
    __half2 l = __floats2half2_rn(a - hf.x, b - hf.y);
    hi = *reinterpret_cast<uint32_t*>(&h);
    lo = *reinterpret_cast<uint32_t*>(&l);
}
__device__ __forceinline__ uint32_t smem_u32(const void* p) {
    uint32_t a;
    asm("{ .reg .u64 t; cvta.to.shared.u64 t, %1; cvt.u32.u64 %0, t; }"
        : "=r"(a) : "l"(p));
    return a;
}
__device__ __forceinline__ void cp16(uint32_t dst, const void* src) {
    asm volatile("cp.async.cg.shared.global [%0], [%1], 16;"
                 :: "r"(dst), "l"(src));
}
#define CP_COMMIT() asm volatile("cp.async.commit_group;" ::: "memory")
#define CP_WAIT0()  asm volatile("cp.async.wait_group 0;" ::: "memory")

#define MMA_F16(d, a0, a1, a2, a3, b0, b1)                                     \
    asm volatile(                                                              \
        "mma.sync.aligned.m16n8k16.row.col.f32.f16.f16.f32 "                   \
        "{%0,%1,%2,%3},{%4,%5,%6,%7},{%8,%9},{%0,%1,%2,%3};"                   \
        : "+f"((d)[0]), "+f"((d)[1]), "+f"((d)[2]), "+f"((d)[3])               \
        : "r"(a0), "r"(a1), "r"(a2), "r"(a3), "r"(b0), "r"(b1))

#define LDSM_X4(R0, R1, R2, R3, ADDR)                                          \
    asm volatile("ldmatrix.sync.aligned.m8n8.x4.shared.b16 {%0,%1,%2,%3},[%4];"\
                 : "=r"(R0), "=r"(R1), "=r"(R2), "=r"(R3) : "r"(ADDR))
#define LDSM_X4T(R0, R1, R2, R3, ADDR)                                         \
    asm volatile("ldmatrix.sync.aligned.m8n8.x4.trans.shared.b16 "             \
                 "{%0,%1,%2,%3},[%4];"                                         \
                 : "=r"(R0), "=r"(R1), "=r"(R2), "=r"(R3) : "r"(ADDR))

// ---------------------------------------------------------------------------
// Pre-pass kernels
// ---------------------------------------------------------------------------
__global__ __launch_bounds__(256) void split_kernel(
    const float* __restrict__ in, __half* __restrict__ oh,
    __half* __restrict__ ol, int n4)
{
    int i = blockIdx.x * 256 + threadIdx.x;
    if (i >= n4) return;
    float4 v = *(const float4*)(in + (size_t)i * 4);
    uint32_t h0, l0, h1, l1;
    split2(v.x, v.y, h0, l0);
    split2(v.z, v.w, h1, l1);
    *(uint2*)(oh + (size_t)i * 4) = make_uint2(h0, h1);
    *(uint2*)(ol + (size_t)i * 4) = make_uint2(l0, l1);
}

// out[C][R] = split(in[R][C])
__global__ __launch_bounds__(256) void transpose_split_kernel(
    const float* __restrict__ in, __half* __restrict__ oh,
    __half* __restrict__ ol, int R, int Cc)
{
    __shared__ float tile[32][33];
    int c0 = blockIdx.x * 32, r0 = blockIdx.y * 32;
    int lx = threadIdx.x & 31, ly = threadIdx.x >> 5;
#pragma unroll
    for (int rr = ly; rr < 32; rr += 8)
        tile[rr][lx] = in[(size_t)(r0 + rr) * Cc + c0 + lx];
    __syncthreads();
#pragma unroll
    for (int rr = ly; rr < 32; rr += 8) {
        float v = tile[lx][rr];
        __half h = __float2half_rn(v);
        __half l = __float2half_rn(v - __half2float(h));
        oh[(size_t)(c0 + rr) * R + r0 + lx] = h;
        ol[(size_t)(c0 + rr) * R + r0 + lx] = l;
    }
}

// ---------------------------------------------------------------------------
// fp16x3 GEMM (pre-split operands): C = A@BT^T + bias
// BM=128, BN=128, BK=32 halves; 256 threads (8 warps 4x2); warp tile 32x64.
// Smem rows: 32 halves = 4 chunks x 16B, chunk XOR (row&3). ldmatrix frags.
// ---------------------------------------------------------------------------
#define G_BUF 32768   // bytes per double-buffer slot (4 regions x 8KB)

template<bool SPLIT_OUT>
__global__ __launch_bounds__(256) void gemm_h2_kernel(
    const __half* __restrict__ Ah, const __half* __restrict__ Al,
    const __half* __restrict__ Bh, const __half* __restrict__ Bl,
    const float* __restrict__ bias,
    float* __restrict__ Cf, __half* __restrict__ Ch, __half* __restrict__ Cl,
    int M, int Nn, int K)
{
    extern __shared__ char smc[];
    const uint32_t sb = smem_u32(smc);

    const int t    = threadIdx.x;
    const int lane = t & 31, wid = t >> 5;
    const int g    = lane >> 2, tg = lane & 3;
    const int wm   = wid >> 1, wn = wid & 1;
    const int m0   = blockIdx.y * 128;
    const int n0   = blockIdx.x * 128;

    // gmem->smem mapping: per region, thread covers row t>>1, chunks 2(t&1),2(t&1)+1
    const int ldrow = t >> 1;
    const int ldc0  = (t & 1) * 2;
    const __half* __restrict__ arrs[4] = {Ah, Al, Bh, Bl};
    const int rowb[4] = {m0, m0, n0, n0};

    // ldmatrix address components (region-relative byte offsets)
    const int arow[2] = {wm * 32 + (lane & 15), wm * 32 + 16 + (lane & 15)};
    const int acb = lane >> 4;                 // chunk bit from lane
    const int brow[4] = {
        wn * 64 + 0  + ((lane >> 4) << 3) + (lane & 7),
        wn * 64 + 16 + ((lane >> 4) << 3) + (lane & 7),
        wn * 64 + 32 + ((lane >> 4) << 3) + (lane & 7),
        wn * 64 + 48 + ((lane >> 4) << 3) + (lane & 7)};
    const int bcb = (lane >> 3) & 1;

    float acc[2][8][4];
#pragma unroll
    for (int mt = 0; mt < 2; mt++)
#pragma unroll
        for (int nt = 0; nt < 8; nt++)
#pragma unroll
            for (int i = 0; i < 4; i++) acc[mt][nt][i] = 0.0f;

    const int NT = K / 32;

    // issue tile kt into buffer bb
    auto issue = [&](int kt, int bb) {
#pragma unroll
        for (int r = 0; r < 4; r++) {
#pragma unroll
            for (int j = 0; j < 2; j++) {
                int ch = ldc0 + j;
                const __half* src = arrs[r] +
                    (size_t)(rowb[r] + ldrow) * K + kt * 32 + ch * 8;
                uint32_t dst = sb + bb * G_BUF + r * 8192 +
                    (ldrow * 4 + (ch ^ (ldrow & 3))) * 16;
                cp16(dst, src);
            }
        }
        CP_COMMIT();
    };

    issue(0, 0);

    for (int kt = 0; kt < NT; kt++) {
        const int b = kt & 1;
        CP_WAIT0();
        __syncthreads();
        if (kt + 1 < NT) issue(kt + 1, b ^ 1);

        const uint32_t bufb = sb + b * G_BUF;
#pragma unroll
        for (int kc = 0; kc < 2; kc++) {
            uint32_t ah[2][4], al[2][4];
#pragma unroll
            for (int mt = 0; mt < 2; mt++) {
                int ch = kc * 2 + acb;
                uint32_t ad = bufb + (arow[mt] * 4 + (ch ^ (arow[mt] & 3))) * 16;
                LDSM_X4(ah[mt][0], ah[mt][1], ah[mt][2], ah[mt][3], ad);
                LDSM_X4(al[mt][0], al[mt][1], al[mt][2], al[mt][3], ad + 8192);
            }
#pragma unroll
            for (int p = 0; p < 4; p++) {
                int ch = kc * 2 + bcb;
                uint32_t bd = bufb + 16384 +
                    (brow[p] * 4 + (ch ^ (brow[p] & 3))) * 16;
                uint32_t bh[4], bl[4];
                LDSM_X4(bh[0], bh[1], bh[2], bh[3], bd);
                LDSM_X4(bl[0], bl[1], bl[2], bl[3], bd + 8192);
#pragma unroll
                for (int e = 0; e < 2; e++) {
                    uint32_t bh0 = e ? bh[2] : bh[0], bh1 = e ? bh[3] : bh[1];
                    uint32_t bl0 = e ? bl[2] : bl[0], bl1 = e ? bl[3] : bl[1];
#pragma unroll
                    for (int mt = 0; mt < 2; mt++) {
                        float* d = acc[mt][2 * p + e];
                        MMA_F16(d, ah[mt][0], ah[mt][1], ah[mt][2], ah[mt][3], bh0, bh1);
                        MMA_F16(d, ah[mt][0], ah[mt][1], ah[mt][2], ah[mt][3], bl0, bl1);
                        MMA_F16(d, al[mt][0], al[mt][1], al[mt][2], al[mt][3], bh0, bh1);
                    }
                }
            }
        }
        __syncthreads();
    }

    // epilogue
#pragma unroll
    for (int mt = 0; mt < 2; mt++) {
        int r0 = m0 + wm * 32 + mt * 16 + g;
#pragma unroll
        for (int nt = 0; nt < 8; nt++) {
            int cc = n0 + wn * 64 + nt * 8 + tg * 2;
            float2 bv = *(const float2*)(bias + cc);
            float* d = acc[mt][nt];
            float v0 = d[0] + bv.x, v1 = d[1] + bv.y;
            float v2 = d[2] + bv.x, v3 = d[3] + bv.y;
            if (SPLIT_OUT) {
                uint32_t h, l;
                split2(v0, v1, h, l);
                *(uint32_t*)(Ch + (size_t)r0 * Nn + cc) = h;
                *(uint32_t*)(Cl + (size_t)r0 * Nn + cc) = l;
                split2(v2, v3, h, l);
                *(uint32_t*)(Ch + (size_t)(r0 + 8) * Nn + cc) = h;
                *(uint32_t*)(Cl + (size_t)(r0 + 8) * Nn + cc) = l;
            } else {
                *(float2*)(Cf + (size_t)r0 * Nn + cc) = make_float2(v0, v1);
                *(float2*)(Cf + (size_t)(r0 + 8) * Nn + cc) = make_float2(v2, v3);
            }
        }
    }
}

// ---------------------------------------------------------------------------
// Flash attention, fp16x3, pre-split inputs, ldmatrix fragments.
// CTA = 128 q-rows x one (b,h); 8 warps, each 16 q-rows. K/V double-buffered.
// Smem rows: 64 halves = 8 chunks x 16B, chunk XOR (row&7).
// Layout: Qh 0 | Ql 16K | buf0 {Kh,Kl,Vh,Vl @8K} 32K | buf1 64K. Total 96K.
// ---------------------------------------------------------------------------
#define ATT_SMEM 98304
#define AKV_BASE 32768

__global__ __launch_bounds__(256) void attn_h2_kernel(
    const __half* __restrict__ qh, const __half* __restrict__ ql,
    __half* __restrict__ oh, __half* __restrict__ ol)
{
    extern __shared__ char smc[];
    const uint32_t sb = smem_u32(smc);

    const int t    = threadIdx.x;
    const int lane = t & 31, wid = t >> 5;
    const int g    = lane >> 2, tg = lane & 3;
    const int q0   = blockIdx.x * 128;
    const int h    = blockIdx.y;
    const int b    = blockIdx.z;
    const size_t rowbase = (size_t)b * NTOK;

    // ldmatrix row components
    const int qrow = wid * 16 + (lane & 15);     // A-frag rows (fixed per thread)
    const int qcb  = lane >> 4;
    const int krow[4] = {                        // K B-frag rows per octet-pair
        0  + ((lane >> 4) << 3) + (lane & 7),
        16 + ((lane >> 4) << 3) + (lane & 7),
        32 + ((lane >> 4) << 3) + (lane & 7),
        48 + ((lane >> 4) << 3) + (lane & 7)};
    const int kcb = (lane >> 3) & 1;
    const int vrow[2] = {                        // V .trans rows per s-group
        ( (lane >> 4)      ) * 16 + (((lane >> 3) & 1) << 3) + (lane & 7),
        ( (lane >> 4) + 2  ) * 16 + (((lane >> 3) & 1) << 3) + (lane & 7)};

    // ---- issue Q (16 cp/thread) + KV tile 0 ----
    {
#pragma unroll
        for (int hl = 0; hl < 2; hl++) {
            const __half* arr = hl ? ql : qh;
#pragma unroll
            for (int j = 0; j < 4; j++) {
                int id = t * 4 + j, row = id >> 3, ch = id & 7;
                const __half* src = arr + (rowbase + q0 + row) * D3 + h * 64 + ch * 8;
                uint32_t dst = sb + hl * 16384 + (row * 8 + (ch ^ (row & 7))) * 16;
                cp16(dst, src);
            }
        }
    }
    auto issue_kv = [&](int kt, int bb) {
        const int k0 = kt * 64;
#pragma unroll
        for (int r = 0; r < 4; r++) {
            const __half* arr = (r & 1) ? ql : qh;
            const int colb = ((r >> 1) ? 2 * DMODEL : DMODEL) + h * 64;
#pragma unroll
            for (int j = 0; j < 2; j++) {
                int id = t * 2 + j, row = id >> 3, ch = id & 7;
                const __half* src = arr + (rowbase + k0 + row) * D3 + colb + ch * 8;
                uint32_t dst = sb + AKV_BASE + bb * 32768 + r * 8192 +
                               (row * 8 + (ch ^ (row & 7))) * 16;
                cp16(dst, src);
            }
        }
        CP_COMMIT();
    };
    issue_kv(0, 0);

    float m0f = -1e30f, m1f = -1e30f, l0 = 0.0f, l1 = 0.0f;
    float oacc[8][4];
#pragma unroll
    for (int nt = 0; nt < 8; nt++)
#pragma unroll
        for (int i = 0; i < 4; i++) oacc[nt][i] = 0.0f;

    for (int kt = 0; kt < NTOK / 64; kt++) {
        const int bb = kt & 1;
        CP_WAIT0();
        __syncthreads();
        if (kt + 1 < NTOK / 64) issue_kv(kt + 1, bb ^ 1);

        const uint32_t kvb = sb + AKV_BASE + bb * 32768;

        // ---- S = Q K^T (3-term) ----
        float sacc[8][4];
#pragma unroll
        for (int nt = 0; nt < 8; nt++)
#pragma unroll
            for (int i = 0; i < 4; i++) sacc[nt][i] = 0.0f;

#pragma unroll
        for (int ks = 0; ks < 4; ks++) {
            int qch = ks * 2 + qcb;
            uint32_t qa = sb + (qrow * 8 + (qch ^ (qrow & 7))) * 16;
            uint32_t Qh_[4], Ql_[4];
            LDSM_X4(Qh_[0], Qh_[1], Qh_[2], Qh_[3], qa);
            LDSM_X4(Ql_[0], Ql_[1], Ql_[2], Ql_[3], qa + 16384);
#pragma unroll
            for (int p = 0; p < 4; p++) {
                int kch = ks * 2 + kcb;
                uint32_t ka = kvb + (krow[p] * 8 + (kch ^ (krow[p] & 7))) * 16;
                uint32_t Kh_[4], Kl_[4];
                LDSM_X4(Kh_[0], Kh_[1], Kh_[2], Kh_[3], ka);
                LDSM_X4(Kl_[0], Kl_[1], Kl_[2], Kl_[3], ka + 8192);
#pragma unroll
                for (int e = 0; e < 2; e++) {
                    uint32_t bh0 = e ? Kh_[2] : Kh_[0], bh1 = e ? Kh_[3] : Kh_[1];
                    uint32_t bl0 = e ? Kl_[2] : Kl_[0], bl1 = e ? Kl_[3] : Kl_[1];
                    float* d = sacc[2 * p + e];
                    MMA_F16(d, Qh_[0], Qh_[1], Qh_[2], Qh_[3], bh0, bh1);
                    MMA_F16(d, Qh_[0], Qh_[1], Qh_[2], Qh_[3], bl0, bl1);
                    MMA_F16(d, Ql_[0], Ql_[1], Ql_[2], Ql_[3], bh0, bh1);
                }
            }
        }

        // ---- online softmax ----
        float mx0 = -1e30f, mx1 = -1e30f;
#pragma unroll
        for (int nt = 0; nt < 8; nt++) {
            sacc[nt][0] *= SCALE; sacc[nt][1] *= SCALE;
            sacc[nt][2] *= SCALE; sacc[nt][3] *= SCALE;
            mx0 = fmaxf(mx0, fmaxf(sacc[nt][0], sacc[nt][1]));
            mx1 = fmaxf(mx1, fmaxf(sacc[nt][2], sacc[nt][3]));
        }
        mx0 = fmaxf(mx0, __shfl_xor_sync(0xffffffffu, mx0, 1));
        mx0 = fmaxf(mx0, __shfl_xor_sync(0xffffffffu, mx0, 2));
        mx1 = fmaxf(mx1, __shfl_xor_sync(0xffffffffu, mx1, 1));
        mx1 = fmaxf(mx1, __shfl_xor_sync(0xffffffffu, mx1, 2));
        float mn0 = fmaxf(m0f, mx0), mn1 = fmaxf(m1f, mx1);
        float c0 = __expf(m0f - mn0), c1 = __expf(m1f - mn1);
        m0f = mn0; m1f = mn1;
        float s0 = 0.0f, s1 = 0.0f;
#pragma unroll
        for (int nt = 0; nt < 8; nt++) {
            sacc[nt][0] = __expf(sacc[nt][0] - mn0);
            sacc[nt][1] = __expf(sacc[nt][1] - mn0);
            sacc[nt][2] = __expf(sacc[nt][2] - mn1);
            sacc[nt][3] = __expf(sacc[nt][3] - mn1);
            s0 += sacc[nt][0] + sacc[nt][1];
            s1 += sacc[nt][2] + sacc[nt][3];
        }
        s0 += __shfl_xor_sync(0xffffffffu, s0, 1);
        s0 += __shfl_xor_sync(0xffffffffu, s0, 2);
        s1 += __shfl_xor_sync(0xffffffffu, s1, 1);
        s1 += __shfl_xor_sync(0xffffffffu, s1, 2);
        l0 = l0 * c0 + s0;
        l1 = l1 * c1 + s1;
#pragma unroll
        for (int nt = 0; nt < 8; nt++) {
            oacc[nt][0] *= c0; oacc[nt][1] *= c0;
            oacc[nt][2] *= c1; oacc[nt][3] *= c1;
        }

        // ---- P fragments (registers; S C-frag == PV A-frag layout) ----
        uint32_t ph[4][4], pl[4][4];
#pragma unroll
        for (int s = 0; s < 4; s++) {
            split2(sacc[2 * s][0],     sacc[2 * s][1],     ph[s][0], pl[s][0]);
            split2(sacc[2 * s][2],     sacc[2 * s][3],     ph[s][1], pl[s][1]);
            split2(sacc[2 * s + 1][0], sacc[2 * s + 1][1], ph[s][2], pl[s][2]);
            split2(sacc[2 * s + 1][2], sacc[2 * s + 1][3], ph[s][3], pl[s][3]);
        }

        // ---- O += P V (3-term); V B-frags via ldmatrix.trans ----
#pragma unroll
        for (int nt = 0; nt < 8; nt++) {
            uint32_t vh[2][4], vl[2][4];
#pragma unroll
            for (int sg = 0; sg < 2; sg++) {
                uint32_t va = kvb + 16384 +
                    (vrow[sg] * 8 + (nt ^ (vrow[sg] & 7))) * 16;
                LDSM_X4T(vh[sg][0], vh[sg][1], vh[sg][2], vh[sg][3], va);
                LDSM_X4T(vl[sg][0], vl[sg][1], vl[sg][2], vl[sg][3], va + 8192);
            }
            float* d = oacc[nt];
#pragma unroll
            for (int s = 0; s < 4; s++) {
                int sg = s >> 1, o = (s & 1) * 2;
                MMA_F16(d, ph[s][0], ph[s][1], ph[s][2], ph[s][3],
                        vh[sg][o], vh[sg][o + 1]);
                MMA_F16(d, ph[s][0], ph[s][1], ph[s][2], ph[s][3],
                        vl[sg][o], vl[sg][o + 1]);
                MMA_F16(d, pl[s][0], pl[s][1], pl[s][2], pl[s][3],
                        vh[sg][o], vh[sg][o + 1]);
            }
        }
        __syncthreads();
    }

    // ---- epilogue: normalize, split to hi/lo halves ----
    float inv0 = 1.0f / l0, inv1 = 1.0f / l1;
    int r0 = q0 + wid * 16 + g;
#pragma unroll
    for (int nt = 0; nt < 8; nt++) {
        int cc = h * HD + nt * 8 + tg * 2;
        uint32_t hh, ll;
        split2(oacc[nt][0] * inv0, oacc[nt][1] * inv0, hh, ll);
        *(uint32_t*)(oh + (rowbase + r0) * DMODEL + cc) = hh;
        *(uint32_t*)(ol + (rowbase + r0) * DMODEL + cc) = ll;
        split2(oacc[nt][2] * inv1, oacc[nt][3] * inv1, hh, ll);
        *(uint32_t*)(oh + (rowbase + r0 + 8) * DMODEL + cc) = hh;
        *(uint32_t*)(ol + (rowbase + r0 + 8) * DMODEL + cc) = ll;
    }
}

// ---------------------------------------------------------------------------
// Launcher
// ---------------------------------------------------------------------------
extern "C" void kernel_launch(void* const* d_in, const int* in_sizes, int n_in,
                              void* d_out, int out_size)
{
    const float* x    = (const float*)d_in[0];
    const float* Wqkv = (const float*)d_in[1];
    const float* bqkv = (const float*)d_in[2];
    const float* Wout = (const float*)d_in[3];
    const float* bout = (const float*)d_in[4];
    float* out = (float*)d_out;

    __half *xh, *xl, *wqh, *wql, *woh, *wol, *qh, *qlp, *ah, *al;
    cudaGetSymbolAddress((void**)&xh,  g_x_h);
    cudaGetSymbolAddress((void**)&xl,  g_x_l);
    cudaGetSymbolAddress((void**)&wqh, g_wqkvT_h);
    cudaGetSymbolAddress((void**)&wql, g_wqkvT_l);
    cudaGetSymbolAddress((void**)&woh, g_woutT_h);
    cudaGetSymbolAddress((void**)&wol, g_woutT_l);
    cudaGetSymbolAddress((void**)&qh,  g_qkv_h);
    cudaGetSymbolAddress((void**)&qlp, g_qkv_l);
    cudaGetSymbolAddress((void**)&ah,  g_att_h);
    cudaGetSymbolAddress((void**)&al,  g_att_l);

    cudaFuncSetAttribute(gemm_h2_kernel<true>,
                         cudaFuncAttributeMaxDynamicSharedMemorySize, 2 * G_BUF);
    cudaFuncSetAttribute(gemm_h2_kernel<false>,
                         cudaFuncAttributeMaxDynamicSharedMemorySize, 2 * G_BUF);
    cudaFuncSetAttribute(attn_h2_kernel,
                         cudaFuncAttributeMaxDynamicSharedMemorySize, ATT_SMEM);

    // 0) pre-split x; transpose+split weights
    split_kernel<<<(MROWS * DMODEL / 4 + 255) / 256, 256>>>(x, xh, xl,
                                                            MROWS * DMODEL / 4);
    transpose_split_kernel<<<dim3(D3 / 32, DMODEL / 32), 256>>>(Wqkv, wqh, wql,
                                                                DMODEL, D3);
    transpose_split_kernel<<<dim3(DMODEL / 32, DMODEL / 32), 256>>>(Wout, woh, wol,
                                                                    DMODEL, DMODEL);

    // 1) QKV projection -> split halves
    {
        dim3 grid(D3 / 128, MROWS / 128);
        gemm_h2_kernel<true><<<grid, 256, 2 * G_BUF>>>(
            xh, xl, wqh, wql, bqkv, nullptr, qh, qlp, MROWS, D3, DMODEL);
    }
    // 2) Attention -> split halves
    {
        dim3 grid(NTOK / 128, NH, BB);
        attn_h2_kernel<<<grid, 256, ATT_SMEM>>>(qh, qlp, ah, al);
    }
    // 3) Output projection -> fp32 out
    {
        dim3 grid(DMODEL / 128, MROWS / 128);
        gemm_h2_kernel<false><<<grid, 256, 2 * G_BUF>>>(
            ah, al, woh, wol, bout, out, nullptr, nullptr, MROWS, DMODEL, DMODEL);
    }
}